// round 2
// baseline (speedup 1.0000x reference)
#include <cuda_runtime.h>
#include <math.h>

#define BB      2
#define NNODES  512
#define NCGC    64
#define FDIM    128
#define NRBF    20
#define NCONVS  3
#define ETOT    32768
#define BN      (BB*NNODES)      // 1024
#define CUT     5.0f
#define PI_F    3.14159265358979323846f
#define PMSG    4096
#define PCON    1024
#define DMAXC   10.0f
#define ACH     8                 // a-chunks in contract kernel
#define ACHUNK  (NNODES/ACH)      // 64

// ---------------- persistent device scratch (no allocs allowed) ----------------
__device__ float  g_h[2][BN*FDIM];
__device__ float4 g_v[2][BN*FDIM];
__device__ float  g_phi[BN*384];
__device__ float  g_phic[BN*384];
__device__ float  g_Tmsg[NCONVS*PMSG*384];
__device__ float  g_Tcon[NCONVS*PCON*384];
__device__ float  g_ed[ETOT];
__device__ float4 g_un[ETOT];
__device__ int    g_pi[ETOT], g_pj[ETOT];
__device__ int    g_cnt[BN], g_fill[BN], g_ptrn[BN+1];
__device__ int    g_csr[ETOT];

__device__ __forceinline__ float silu(float x) { return x / (1.f + expf(-x)); }

// ---------------- init: copy h, zero v, init output, zero CSR counters ----------------
__global__ void k_init(const float* __restrict__ h_in, const float* __restrict__ H_in,
                       float* __restrict__ out)
{
    int idx = blockIdx.x*blockDim.x + threadIdx.x;
    int stride = gridDim.x*blockDim.x;
    for (int i = idx; i < BN*FDIM; i += stride) {
        g_h[0][i] = h_in[i];
        g_v[0][i] = make_float4(0.f,0.f,0.f,0.f);
    }
    for (int i = idx; i < BB*NCGC*FDIM*4; i += stride)
        out[i] = (i < BB*NCGC*FDIM) ? H_in[i] : 0.f;
    for (int i = idx; i < BN; i += stride) { g_cnt[i]=0; g_fill[i]=0; }
}

// ---------------- edge geometry + degree count (skip edges with d>=CUT: env==0) ----------------
__global__ void k_geom(const int* __restrict__ nbr, const float* __restrict__ xyz)
{
    int e = blockIdx.x*256 + threadIdx.x;
    if (e >= ETOT) return;
    int b  = nbr[3*e], ii = nbr[3*e+1], jj = nbr[3*e+2];
    int pi = b*NNODES + ii, pj = b*NNODES + jj;
    g_pi[e] = pi; g_pj[e] = pj;
    float rx = xyz[3*pi]   - xyz[3*pj];
    float ry = xyz[3*pi+1] - xyz[3*pj+1];
    float rz = xyz[3*pi+2] - xyz[3*pj+2];
    float d = sqrtf(rx*rx + ry*ry + rz*rz);
    g_ed[e] = d;
    float inv = 1.f/d;
    g_un[e] = make_float4(rx*inv, ry*inv, rz*inv, 0.f);
    if (d < CUT) atomicAdd(&g_cnt[pi], 1);
}

// ---------------- exclusive scan of degrees (1024 entries, one block) ----------------
__global__ void k_scan()
{
    __shared__ int s[BN];
    int t = threadIdx.x;
    s[t] = g_cnt[t];
    __syncthreads();
    for (int off = 1; off < BN; off <<= 1) {
        int x = (t >= off) ? s[t-off] : 0;
        __syncthreads();
        s[t] += x;
        __syncthreads();
    }
    g_ptrn[t+1] = s[t];
    if (t == 0) g_ptrn[0] = 0;
}

// ---------------- CSR fill ----------------
__global__ void k_fill()
{
    int e = blockIdx.x*256 + threadIdx.x;
    if (e >= ETOT) return;
    if (g_ed[e] >= CUT) return;
    int pi = g_pi[e];
    int pos = g_ptrn[pi] + atomicAdd(&g_fill[pi], 1);
    g_csr[pos] = e;
}

// ---------------- message table: Tmsg[t][p][m] = env(d)*(rbf(d)@We[t] + be[t])[m] ----------------
__global__ void k_msg_table(const float* __restrict__ We, const float* __restrict__ be)
{
    int p = blockIdx.x, t = blockIdx.y, tid = threadIdx.x; // 128 threads
    float d  = p * (CUT/(PMSG-1));
    float dd = fmaxf(d, 1e-6f);
    float env = (d < CUT) ? 0.5f*(cosf(PI_F*d/CUT) + 1.f) : 0.f;
    __shared__ float rb[NRBF];
    if (tid < NRBF) rb[tid] = sinf((tid+1)*PI_F/CUT*dd)/dd;
    __syncthreads();
    const float* Wt = We + t*NRBF*384;
    const float* bt = be + t*384;
    #pragma unroll
    for (int mm = 0; mm < 3; mm++) {
        int m = tid + (mm<<7);
        float acc = bt[m];
        #pragma unroll
        for (int k = 0; k < NRBF; k++) acc += rb[k]*Wt[k*384+m];
        g_Tmsg[(t*PMSG+p)*384 + m] = acc*env;
    }
}

// ---------------- contraction table (bias kept separate, columns remapped to [e3][f]) ----------------
// Tcon[t][p][e3*128+f] = sum_k exp(-(d_p - off_k)^2) * Wf[t][k][f*3+e3]
__global__ void k_con_table(const float* __restrict__ Wf)
{
    __shared__ float es[16][FDIM];
    int tid = threadIdx.x;              // 384 threads
    int p0  = blockIdx.x*16, t = blockIdx.y;
    const float step = DMAXC/(PCON-1);
    for (int i = tid; i < 16*FDIM; i += 384) {
        int pl = i >> 7, k = i & 127;
        float d = (p0+pl)*step;
        float o = CUT*k/127.f;
        float x = d - o;
        es[pl][k] = expf(-x*x);
    }
    __syncthreads();
    int src = (tid & 127)*3 + (tid >> 7);
    float acc[16];
    #pragma unroll
    for (int p = 0; p < 16; p++) acc[p] = 0.f;
    const float* Wt = Wf + t*FDIM*384;
    for (int k = 0; k < FDIM; k++) {
        float w = Wt[k*384 + src];
        #pragma unroll
        for (int p = 0; p < 16; p++) acc[p] += es[p][k]*w;
    }
    for (int p = 0; p < 16; p++)
        g_Tcon[(t*PCON + p0 + p)*384 + tid] = acc[p];
}

// ---------------- fused 2-layer MLP: out = silu(h@W1+b1)@W2+b2, 8 nodes/block ----------------
// dst_sel: 0 -> g_phi (natural m order), 1 -> g_phic (remap m=(f*3+e3) -> e3*128+f)
__global__ void __launch_bounds__(256) k_mlp(int hsel,
                      const float* __restrict__ W1, const float* __restrict__ b1,
                      const float* __restrict__ W2, const float* __restrict__ b2, int dst_sel)
{
    __shared__ float h_s[8][FDIM];
    __shared__ float hid_s[8][FDIM];
    int t = threadIdx.x;                // 256
    int nb = blockIdx.x*8;
    const float* hb = g_h[hsel];
    for (int i = t; i < 8*FDIM; i += 256)
        h_s[i>>7][i&127] = hb[(nb + (i>>7))*FDIM + (i&127)];
    __syncthreads();
    int g = t & 127, half = t >> 7;
    int n0 = half*4;
    {
        float bg = b1[g];
        float a0=bg, a1=bg, a2=bg, a3=bg;
        #pragma unroll 4
        for (int f = 0; f < FDIM; f++) {
            float w = W1[f*FDIM + g];
            a0 += h_s[n0  ][f]*w;
            a1 += h_s[n0+1][f]*w;
            a2 += h_s[n0+2][f]*w;
            a3 += h_s[n0+3][f]*w;
        }
        hid_s[n0  ][g] = silu(a0);
        hid_s[n0+1][g] = silu(a1);
        hid_s[n0+2][g] = silu(a2);
        hid_s[n0+3][g] = silu(a3);
    }
    __syncthreads();
    float* dst = dst_sel ? g_phic : g_phi;
    #pragma unroll
    for (int mm = 0; mm < 3; mm++) {
        int m = g + (mm<<7);
        float b = b2[m];
        float a0=b, a1=b, a2=b, a3=b;
        #pragma unroll 4
        for (int k = 0; k < FDIM; k++) {
            float w = W2[k*384 + m];
            a0 += hid_s[n0  ][k]*w;
            a1 += hid_s[n0+1][k]*w;
            a2 += hid_s[n0+2][k]*w;
            a3 += hid_s[n0+3][k]*w;
        }
        int oi = dst_sel ? (((m % 3) << 7) + (m / 3)) : m;
        dst[(nb+n0  )*384 + oi] = a0;
        dst[(nb+n0+1)*384 + oi] = a1;
        dst[(nb+n0+2)*384 + oi] = a2;
        dst[(nb+n0+3)*384 + oi] = a3;
    }
}

// ---------------- edge message pass (CSR gather, register accumulation) ----------------
__global__ void __launch_bounds__(128) k_edge(int t, int cur, int nxt)
{
    int i = blockIdx.x, f = threadIdx.x;
    int e0 = g_ptrn[i], e1 = g_ptrn[i+1];
    const float*  Tm   = g_Tmsg + t*PMSG*384;
    const float*  phi  = g_phi;
    const float4* vcur = g_v[cur];
    const float inv_step = (PMSG-1)/CUT;
    float acch = 0.f, av0 = 0.f, av1 = 0.f, av2 = 0.f;
    for (int q = e0; q < e1; q++) {
        int e = g_csr[q];
        float d = g_ed[e];
        float u = d*inv_step;
        int idx = (int)u; if (idx > PMSG-2) idx = PMSG-2;
        float fr = u - idx;
        const float* ba = Tm + idx*384;
        float w0 = ba[f]     + fr*(ba[384+f] - ba[f]);
        float w1 = ba[128+f] + fr*(ba[512+f] - ba[128+f]);
        float w2 = ba[256+f] + fr*(ba[640+f] - ba[256+f]);
        int pj = g_pj[e];
        const float* pp = phi + pj*384;
        float i0 = pp[f]*w0, i1 = pp[128+f]*w1, i2 = pp[256+f]*w2;
        float4 uq = g_un[e];
        float4 vj = vcur[pj*FDIM + f];
        acch += i1;
        av0  += i2*uq.x + i0*vj.x;
        av1  += i2*uq.y + i0*vj.y;
        av2  += i2*uq.z + i0*vj.z;
    }
    g_h[nxt][i*FDIM+f] = g_h[cur][i*FDIM+f] + 0.5f*acch;
    float4 vc = vcur[i*FDIM+f];
    g_v[nxt][i*FDIM+f] = make_float4(vc.x + 0.5f*av0, vc.y + 0.5f*av1, vc.z + 0.5f*av2, 0.f);
}

// ---------------- node update (PaiNN-style), 4 nodes/block, in-place on buffer `buf` ----------------
__global__ void __launch_bounds__(128) k_update(const float* __restrict__ U, const float* __restrict__ Vm,
                         const float* __restrict__ W1, const float* __restrict__ b1,
                         const float* __restrict__ W2, const float* __restrict__ b2, int buf)
{
    __shared__ float  h_s[4][FDIM];
    __shared__ float4 v_s[4][FDIM];
    __shared__ float4 uv_s[4][FDIM];
    __shared__ float4 vv_s[4][FDIM];
    __shared__ float  vn_s[4][FDIM];
    __shared__ float  hid_s[4][FDIM];
    __shared__ float  a_s[4][384];
    int g = threadIdx.x;
    int nb = blockIdx.x*4;
    float*  hb = g_h[buf];
    float4* vb = g_v[buf];
    #pragma unroll
    for (int n = 0; n < 4; n++) {
        h_s[n][g] = hb[(nb+n)*FDIM + g];
        v_s[n][g] = vb[(nb+n)*FDIM + g];
    }
    __syncthreads();
    {
        float au[4][3], av[4][3];
        #pragma unroll
        for (int n = 0; n < 4; n++)
            #pragma unroll
            for (int e = 0; e < 3; e++) { au[n][e]=0.f; av[n][e]=0.f; }
        for (int f = 0; f < FDIM; f++) {
            float uu = U[f*FDIM+g], vv = Vm[f*FDIM+g];
            #pragma unroll
            for (int n = 0; n < 4; n++) {
                float4 x = v_s[n][f];
                au[n][0] += x.x*uu; au[n][1] += x.y*uu; au[n][2] += x.z*uu;
                av[n][0] += x.x*vv; av[n][1] += x.y*vv; av[n][2] += x.z*vv;
            }
        }
        #pragma unroll
        for (int n = 0; n < 4; n++) {
            uv_s[n][g] = make_float4(au[n][0], au[n][1], au[n][2], 0.f);
            vv_s[n][g] = make_float4(av[n][0], av[n][1], av[n][2], 0.f);
            vn_s[n][g] = sqrtf(av[n][0]*av[n][0] + av[n][1]*av[n][1] + av[n][2]*av[n][2] + 1e-15f);
        }
    }
    __syncthreads();
    {
        float ac[4];
        float bg = b1[g];
        #pragma unroll
        for (int n = 0; n < 4; n++) ac[n] = bg;
        for (int f = 0; f < FDIM; f++) {
            float w = W1[f*FDIM + g];
            #pragma unroll
            for (int n = 0; n < 4; n++) ac[n] += h_s[n][f]*w;
        }
        for (int f = 0; f < FDIM; f++) {
            float w = W1[(FDIM+f)*FDIM + g];
            #pragma unroll
            for (int n = 0; n < 4; n++) ac[n] += vn_s[n][f]*w;
        }
        #pragma unroll
        for (int n = 0; n < 4; n++) hid_s[n][g] = silu(ac[n]);
    }
    __syncthreads();
    #pragma unroll
    for (int mm = 0; mm < 3; mm++) {
        int m = g + (mm<<7);
        float b = b2[m];
        float a0=b, a1=b, a2=b, a3=b;
        for (int k = 0; k < FDIM; k++) {
            float w = W2[k*384 + m];
            a0 += hid_s[0][k]*w; a1 += hid_s[1][k]*w;
            a2 += hid_s[2][k]*w; a3 += hid_s[3][k]*w;
        }
        a_s[0][m]=a0; a_s[1][m]=a1; a_s[2][m]=a2; a_s[3][m]=a3;
    }
    __syncthreads();
    #pragma unroll
    for (int n = 0; n < 4; n++) {
        float a0 = a_s[n][g], a1 = a_s[n][128+g], a2 = a_s[n][256+g];
        float4 uv = uv_s[n][g], vv = vv_s[n][g];
        float ds = (uv.x*vv.x + uv.y*vv.y + uv.z*vv.z)*a1 + a2;
        hb[(nb+n)*FDIM + g] = h_s[n][g] + 0.5f*ds;
        float4 vo = v_s[n][g];
        vb[(nb+n)*FDIM + g] = make_float4(vo.x + 0.5f*a0*uv.x,
                                          vo.y + 0.5f*a0*uv.y,
                                          vo.z + 0.5f*a0*uv.z, 0.f);
    }
}

// ---------------- contraction: table-lerp w_c, combine with phi_c, reduce over atoms ----------------
__global__ void __launch_bounds__(128) k_contract(int t, int buf,
    const float* __restrict__ bf,
    const float* __restrict__ xyz, const float* __restrict__ cgxyz,
    const float* __restrict__ assign, float* __restrict__ out)
{
    int f  = threadIdx.x;
    int bc = blockIdx.x;
    int b  = bc >> 6, c = bc & 63;
    int a0 = blockIdx.y*ACHUNK;
    const float* Tc = g_Tcon + t*PCON*384;
    const float4* vbuf = g_v[buf];
    float cgx = cgxyz[(b*NCGC+c)*3+0];
    float cgy = cgxyz[(b*NCGC+c)*3+1];
    float cgz = cgxyz[(b*NCGC+c)*3+2];
    float bf0 = bf[f*3+0], bf1 = bf[f*3+1], bf2 = bf[f*3+2];
    const float inv_step = (PCON-1)/DMAXC;
    float hacc = 0.f, vo0 = 0.f, vo1 = 0.f, vo2 = 0.f;
    for (int aa = 0; aa < ACHUNK; aa++) {
        int a = a0 + aa;
        int n = b*NNODES + a;
        float rx = xyz[3*n]   - cgx;
        float ry = xyz[3*n+1] - cgy;
        float rz = xyz[3*n+2] - cgz;
        float d = sqrtf(rx*rx + ry*ry + rz*rz);
        float inv_d = 1.f/d;
        float ux = rx*inv_d, uy = ry*inv_d, uz = rz*inv_d;
        float s = assign[n*NCGC + c];
        float td = d*inv_step;
        int idx = (int)td;
        float fr;
        if (idx > PCON-2) { idx = PCON-2; fr = 1.f; } else fr = td - idx;
        const float* ba = Tc + idx*384;
        float w0 = ba[f]     + fr*(ba[384+f] - ba[f])     + bf0;
        float w1 = ba[128+f] + fr*(ba[512+f] - ba[128+f]) + bf1;
        float w2 = ba[256+f] + fr*(ba[640+f] - ba[256+f]) + bf2;
        const float* pp = g_phic + n*384;
        float x0 = w0*pp[f], x1 = w1*pp[128+f], x2 = w2*pp[256+f];
        float4 vp = vbuf[n*FDIM + f];
        hacc += s*x1;
        vo0  += s*(x2*ux + x0*vp.x);
        vo1  += s*(x2*uy + x0*vp.y);
        vo2  += s*(x2*uz + x0*vp.z);
    }
    atomicAdd(&out[(b*NCGC+c)*FDIM + f], hacc);
    float* vout = out + BB*NCGC*FDIM + ((b*NCGC+c)*FDIM + f)*3;
    atomicAdd(vout+0, vo0);
    atomicAdd(vout+1, vo1);
    atomicAdd(vout+2, vo2);
}

// ---------------- host ----------------
extern "C" void kernel_launch(void* const* d_in, const int* in_sizes, int n_in,
                              void* d_out, int out_size)
{
    const float* h_in   = (const float*)d_in[0];
    const float* H_in   = (const float*)d_in[1];
    const float* xyz    = (const float*)d_in[2];
    const float* cgxyz  = (const float*)d_in[3];
    const float* assign = (const float*)d_in[4];
    const int*   nbr    = (const int*)  d_in[6];
    const float* msgW1  = (const float*)d_in[7];
    const float* msgb1  = (const float*)d_in[8];
    const float* msgW2  = (const float*)d_in[9];
    const float* msgb2  = (const float*)d_in[10];
    const float* We     = (const float*)d_in[11];
    const float* be     = (const float*)d_in[12];
    const float* updU   = (const float*)d_in[13];
    const float* updV   = (const float*)d_in[14];
    const float* updW1  = (const float*)d_in[15];
    const float* updb1  = (const float*)d_in[16];
    const float* updW2  = (const float*)d_in[17];
    const float* updb2  = (const float*)d_in[18];
    const float* conWf  = (const float*)d_in[19];
    const float* conbf  = (const float*)d_in[20];
    const float* conW1  = (const float*)d_in[21];
    const float* conb1  = (const float*)d_in[22];
    const float* conW2  = (const float*)d_in[23];
    const float* conb2  = (const float*)d_in[24];
    float* out = (float*)d_out;

    k_init<<<256, 256>>>(h_in, H_in, out);
    k_geom<<<ETOT/256, 256>>>(nbr, xyz);
    k_scan<<<1, BN>>>();
    k_fill<<<ETOT/256, 256>>>();
    {
        dim3 gm(PMSG, NCONVS);
        k_msg_table<<<gm, 128>>>(We, be);
        dim3 gc(PCON/16, NCONVS);
        k_con_table<<<gc, 384>>>(conWf);
    }

    int cur = 0;
    for (int t = 0; t < NCONVS; t++) {
        int nxt = 1 - cur;
        k_mlp<<<BN/8, 256>>>(cur,
            msgW1 + t*FDIM*FDIM, msgb1 + t*FDIM,
            msgW2 + t*FDIM*384,  msgb2 + t*384, 0);
        k_edge<<<BN, 128>>>(t, cur, nxt);
        k_update<<<BN/4, 128>>>(
            updU + t*FDIM*FDIM, updV + t*FDIM*FDIM,
            updW1 + t*2*FDIM*FDIM, updb1 + t*FDIM,
            updW2 + t*FDIM*384,    updb2 + t*384, nxt);
        k_mlp<<<BN/8, 256>>>(nxt,
            conW1 + t*FDIM*FDIM, conb1 + t*FDIM,
            conW2 + t*FDIM*384,  conb2 + t*384, 1);
        dim3 gk(BB*NCGC, ACH);
        k_contract<<<gk, 128>>>(t, nxt, conbf + t*384, xyz, cgxyz, assign, out);
        cur = nxt;
    }
    (void)in_sizes; (void)n_in; (void)out_size;
}